// round 1
// baseline (speedup 1.0000x reference)
#include <cuda_runtime.h>
#include <math.h>

#define NN 50000
#define NE 800000
#define DIN 96
#define DD 128
#define NB 512
#define MPNN_STEPS 4
#define S2S_STEPS 3

// ---------------- device scratch (no allocation allowed) ----------------
__device__ int g_src[NE];
__device__ int g_dst[NE];
__device__ int g_batch[NN];
__device__ int g_cnt[NN];          // in-degree counts
__device__ int g_off[NN + 1];      // CSR offsets by dst
__device__ int g_cursor[NN];
__device__ int g_csr[NE];          // src ids grouped by dst
__device__ int g_bcnt[NB];
__device__ int g_gstart[NB + 1];   // graph segment starts (batch is sorted)
__device__ __align__(16) float g_h0[NN * DD];
__device__ __align__(16) float g_h1[NN * DD];
__device__ float g_e[NN];
__device__ __align__(16) float g_qstar[NB * 2 * DD];
__device__ __align__(16) float g_hh[NB * DD];
__device__ __align__(16) float g_cc[NB * DD];
__device__ float g_gates[NB * 4 * DD];
__device__ int g_flags[2];         // [0]: edge_index is int64, [1]: batch is int64

// ---------------- dtype detection (int64 vs int32, deterministic) --------
__global__ void detect_kernel(const int* ei, const int* bt) {
    if (blockIdx.x == 0 && threadIdx.x == 0) {
        // if data is int64 with small values, every odd int32 word is 0
        int z = 0;
        for (int i = 0; i < 256; i++) if (ei[2 * i + 1] == 0) z++;
        g_flags[0] = (z >= 192) ? 1 : 0;
        z = 0;
        for (int i = 0; i < 256; i++) if (bt[2 * i + 1] == 0) z++;
        g_flags[1] = (z >= 192) ? 1 : 0;
    }
}

__global__ void zero_kernel() {
    int i = blockIdx.x * blockDim.x + threadIdx.x;
    if (i < NN) g_cnt[i] = 0;
    if (i < NB) g_bcnt[i] = 0;
    if (i < NB * 2 * DD) g_qstar[i] = 0.f;
    if (i < NB * DD) { g_hh[i] = 0.f; g_cc[i] = 0.f; }
}

__global__ void convert_edges(const void* ei) {
    int i = blockIdx.x * blockDim.x + threadIdx.x;
    if (i >= NE) return;
    if (g_flags[0]) {
        const long long* p = (const long long*)ei;
        g_src[i] = (int)p[i];
        g_dst[i] = (int)p[NE + i];
    } else {
        const int* p = (const int*)ei;
        g_src[i] = p[i];
        g_dst[i] = p[NE + i];
    }
}

__global__ void convert_batch(const void* bt) {
    int i = blockIdx.x * blockDim.x + threadIdx.x;
    if (i >= NN) return;
    if (g_flags[1]) {
        const long long* p = (const long long*)bt;
        g_batch[i] = (int)p[i];
    } else {
        g_batch[i] = ((const int*)bt)[i];
    }
}

// ---------------- CSR build ----------------
__global__ void hist_edges() {
    int i = blockIdx.x * blockDim.x + threadIdx.x;
    if (i < NE) atomicAdd(&g_cnt[g_dst[i]], 1);
}
__global__ void hist_batch() {
    int i = blockIdx.x * blockDim.x + threadIdx.x;
    if (i < NN) atomicAdd(&g_bcnt[g_batch[i]], 1);
}

__global__ void scan_nodes() {
    __shared__ int s[1024];
    int t = threadIdx.x;
    const int CH = (NN + 1023) / 1024;  // 49
    int base = t * CH;
    int tot = 0;
    for (int i = 0; i < CH; i++) {
        int idx = base + i;
        if (idx < NN) tot += g_cnt[idx];
    }
    s[t] = tot;
    __syncthreads();
    for (int d = 1; d < 1024; d <<= 1) {
        int v = 0;
        if (t >= d) v = s[t - d];
        __syncthreads();
        s[t] += v;
        __syncthreads();
    }
    int run = s[t] - tot;   // exclusive prefix
    for (int i = 0; i < CH; i++) {
        int idx = base + i;
        if (idx < NN) {
            g_off[idx] = run;
            g_cursor[idx] = run;
            run += g_cnt[idx];
        }
    }
    if (t == 1023) g_off[NN] = NE;
}

__global__ void scan_batch() {
    __shared__ int s[NB];
    int t = threadIdx.x;
    int v0 = g_bcnt[t];
    s[t] = v0;
    __syncthreads();
    for (int d = 1; d < NB; d <<= 1) {
        int v = 0;
        if (t >= d) v = s[t - d];
        __syncthreads();
        s[t] += v;
        __syncthreads();
    }
    g_gstart[t] = s[t] - v0;
    if (t == NB - 1) g_gstart[NB] = NN;
}

__global__ void fill_csr() {
    int i = blockIdx.x * blockDim.x + threadIdx.x;
    if (i >= NE) return;
    int pos = atomicAdd(&g_cursor[g_dst[i]], 1);
    g_csr[pos] = g_src[i];
}

// ---------------- input layer GEMM + relu: h0 = relu(x @ W_in^T + b) ----
// x [NN, 96], W [128, 96] -> h0 [NN, 128]
__global__ void gemm_in(const float* __restrict__ x, const float* __restrict__ W,
                        const float* __restrict__ bias) {
    __shared__ float As[64][33];
    __shared__ float Bs[32][65];
    int tid = threadIdx.x;
    int tx = tid % 16, ty = tid / 16;
    int row0 = blockIdx.x * 64, col0 = blockIdx.y * 64;
    float acc[4][4] = {};
    for (int kt = 0; kt < DIN; kt += 32) {
        for (int l = tid; l < 64 * 32; l += 256) {
            int r = l / 32, k = l % 32;
            As[r][k] = (row0 + r < NN) ? x[(size_t)(row0 + r) * DIN + kt + k] : 0.f;
        }
        for (int l = tid; l < 64 * 32; l += 256) {
            int j = l / 32, k = l % 32;
            Bs[k][j] = W[(size_t)(col0 + j) * DIN + kt + k];
        }
        __syncthreads();
#pragma unroll
        for (int k = 0; k < 32; k++) {
            float a[4], b[4];
#pragma unroll
            for (int i = 0; i < 4; i++) a[i] = As[ty * 4 + i][k];
#pragma unroll
            for (int j = 0; j < 4; j++) b[j] = Bs[k][tx * 4 + j];
#pragma unroll
            for (int i = 0; i < 4; i++)
#pragma unroll
                for (int j = 0; j < 4; j++) acc[i][j] += a[i] * b[j];
        }
        __syncthreads();
    }
    for (int i = 0; i < 4; i++) {
        int r = row0 + ty * 4 + i;
        if (r >= NN) continue;
        for (int j = 0; j < 4; j++) {
            int c = col0 + tx * 4 + j;
            float v = acc[i][j] + bias[c];
            g_h0[(size_t)r * DD + c] = fmaxf(v, 0.f);
        }
    }
}

// ---------------- MPNN step: warp per node, CSR gather, no fp atomics ----
__global__ void mpnn_step(int flip) {
    const float* __restrict__ hin = flip ? g_h1 : g_h0;
    float* __restrict__ hout = flip ? g_h0 : g_h1;
    int warp = (blockIdx.x * blockDim.x + threadIdx.x) >> 5;
    int lane = threadIdx.x & 31;
    if (warp >= NN) return;
    int n = warp;
    int s0 = g_off[n], s1 = g_off[n + 1];
    float4 acc = make_float4(0.f, 0.f, 0.f, 0.f);
    for (int base = s0; base < s1; base += 32) {
        int m = s1 - base;
        int idx = (lane < m) ? g_csr[base + lane] : 0;
        int lim = m < 32 ? m : 32;
        for (int t = 0; t < lim; t++) {
            int s = __shfl_sync(0xffffffffu, idx, t);
            float4 v = *(const float4*)(hin + (size_t)s * DD + lane * 4);
            acc.x += v.x; acc.y += v.y; acc.z += v.z; acc.w += v.w;
        }
    }
    float deg = (float)((s1 - s0) > 1 ? (s1 - s0) : 1);
    float4 hv = *(const float4*)(hin + (size_t)n * DD + lane * 4);
    float4 o;
    o.x = (hv.x + acc.x / deg) * 0.5f;
    o.y = (hv.y + acc.y / deg) * 0.5f;
    o.z = (hv.z + acc.z / deg) * 0.5f;
    o.w = (hv.w + acc.w / deg) * 0.5f;
    *(float4*)(hout + (size_t)n * DD + lane * 4) = o;
}

// ---------------- Set2Set ----------------
// gates = q_star @ W_ih^T + hh @ W_hh^T   (biases added in pointwise)
__global__ void gemm_gates(const float* __restrict__ W_ih, const float* __restrict__ W_hh) {
    __shared__ float As[64][33];
    __shared__ float Bs[32][65];
    int tid = threadIdx.x;
    int tx = tid % 16, ty = tid / 16;
    int r0 = blockIdx.x * 64, c0 = blockIdx.y * 64;
    float acc[4][4] = {};
    for (int kt = 0; kt < 384; kt += 32) {
        for (int l = tid; l < 64 * 32; l += 256) {
            int r = l / 32, k = l % 32;
            int kk = kt + k;
            As[r][k] = (kk < 256) ? g_qstar[(r0 + r) * 256 + kk]
                                  : g_hh[(r0 + r) * DD + (kk - 256)];
        }
        for (int l = tid; l < 64 * 32; l += 256) {
            int j = l / 32, k = l % 32;
            int kk = kt + k;
            Bs[k][j] = (kk < 256) ? W_ih[(size_t)(c0 + j) * 256 + kk]
                                  : W_hh[(size_t)(c0 + j) * DD + (kk - 256)];
        }
        __syncthreads();
#pragma unroll
        for (int k = 0; k < 32; k++) {
            float a[4], b[4];
#pragma unroll
            for (int i = 0; i < 4; i++) a[i] = As[ty * 4 + i][k];
#pragma unroll
            for (int j = 0; j < 4; j++) b[j] = Bs[k][tx * 4 + j];
#pragma unroll
            for (int i = 0; i < 4; i++)
#pragma unroll
                for (int j = 0; j < 4; j++) acc[i][j] += a[i] * b[j];
        }
        __syncthreads();
    }
    for (int i = 0; i < 4; i++)
        for (int j = 0; j < 4; j++)
            g_gates[(r0 + ty * 4 + i) * 512 + c0 + tx * 4 + j] = acc[i][j];
}

__global__ void lstm_pointwise(int first, const float* __restrict__ b_ih,
                               const float* __restrict__ b_hh) {
    int b = blockIdx.x, d = threadIdx.x;
    float gi = first ? 0.f : g_gates[b * 4 * DD + d];
    float gf = first ? 0.f : g_gates[b * 4 * DD + DD + d];
    float gg = first ? 0.f : g_gates[b * 4 * DD + 2 * DD + d];
    float go = first ? 0.f : g_gates[b * 4 * DD + 3 * DD + d];
    gi += b_ih[d] + b_hh[d];
    gf += b_ih[DD + d] + b_hh[DD + d];
    gg += b_ih[2 * DD + d] + b_hh[2 * DD + d];
    go += b_ih[3 * DD + d] + b_hh[3 * DD + d];
    float i = 1.f / (1.f + expf(-gi));
    float f = 1.f / (1.f + expf(-gf));
    float g = tanhf(gg);
    float o = 1.f / (1.f + expf(-go));
    float c = f * g_cc[b * DD + d] + i * g;
    g_cc[b * DD + d] = c;
    g_hh[b * DD + d] = o * tanhf(c);
}

// e[n] = dot(h[n], hh[batch[n]])   (h lives in g_h0 after 4 MPNN steps)
__global__ void e_kernel() {
    int warp = (blockIdx.x * blockDim.x + threadIdx.x) >> 5;
    int lane = threadIdx.x & 31;
    if (warp >= NN) return;
    int n = warp;
    int b = g_batch[n];
    float4 hv = *(const float4*)(g_h0 + (size_t)n * DD + lane * 4);
    float4 qv = *(const float4*)(g_hh + (size_t)b * DD + lane * 4);
    float s = hv.x * qv.x + hv.y * qv.y + hv.z * qv.z + hv.w * qv.w;
#pragma unroll
    for (int d = 16; d > 0; d >>= 1) s += __shfl_down_sync(0xffffffffu, s, d);
    if (lane == 0) g_e[n] = s;
}

// block per graph: softmax over segment + weighted readout r, write q_star
__global__ void graph_reduce() {
    int b = blockIdx.x, t = threadIdx.x;  // 128 threads
    int s = g_gstart[b], e = g_gstart[b + 1];
    __shared__ float red[128];
    __shared__ float w[128];
    float m = -1e30f;
    for (int i = s + t; i < e; i += 128) m = fmaxf(m, g_e[i]);
    red[t] = m;
    __syncthreads();
    for (int d = 64; d > 0; d >>= 1) {
        if (t < d) red[t] = fmaxf(red[t], red[t + d]);
        __syncthreads();
    }
    float emax = red[0];
    __syncthreads();
    float sum = 0.f;
    for (int i = s + t; i < e; i += 128) sum += expf(g_e[i] - emax);
    red[t] = sum;
    __syncthreads();
    for (int d = 64; d > 0; d >>= 1) {
        if (t < d) red[t] += red[t + d];
        __syncthreads();
    }
    float inv = 1.f / (red[0] + 1e-16f);
    __syncthreads();
    float r = 0.f;
    for (int base = s; base < e; base += 128) {
        int i = base + t;
        w[t] = (i < e) ? expf(g_e[i] - emax) * inv : 0.f;
        __syncthreads();
        int lim = e - base;
        if (lim > 128) lim = 128;
        for (int c = 0; c < lim; c++)
            r += w[c] * g_h0[(size_t)(base + c) * DD + t];
        __syncthreads();
    }
    g_qstar[b * 2 * DD + t] = g_hh[b * DD + t];
    g_qstar[b * 2 * DD + DD + t] = r;
}

__global__ void pred_kernel(const float* __restrict__ Wp, const float* __restrict__ bp,
                            float* __restrict__ out) {
    int b = blockIdx.x;
    int lane = threadIdx.x;  // 32
    float s = 0.f;
    for (int k = lane; k < 2 * DD; k += 32) s += g_qstar[b * 2 * DD + k] * Wp[k];
#pragma unroll
    for (int d = 16; d > 0; d >>= 1) s += __shfl_down_sync(0xffffffffu, s, d);
    if (lane == 0) out[b] = s + bp[0];
}

// ---------------- launch ----------------
extern "C" void kernel_launch(void* const* d_in, const int* in_sizes, int n_in,
                              void* d_out, int out_size) {
    const float* x      = (const float*)d_in[0];
    const void*  ei     = d_in[1];
    const void*  bt     = d_in[2];
    const float* W_in   = (const float*)d_in[3];
    const float* b_in   = (const float*)d_in[4];
    const float* W_ih   = (const float*)d_in[5];
    const float* W_hh   = (const float*)d_in[6];
    const float* b_ih   = (const float*)d_in[7];
    const float* b_hh   = (const float*)d_in[8];
    const float* W_pred = (const float*)d_in[9];
    const float* b_pred = (const float*)d_in[10];
    float* out = (float*)d_out;

    detect_kernel<<<1, 32>>>((const int*)ei, (const int*)bt);
    zero_kernel<<<(NB * 2 * DD + 255) / 256, 256>>>();
    convert_edges<<<(NE + 255) / 256, 256>>>(ei);
    convert_batch<<<(NN + 255) / 256, 256>>>(bt);
    hist_edges<<<(NE + 255) / 256, 256>>>();
    hist_batch<<<(NN + 255) / 256, 256>>>();
    scan_nodes<<<1, 1024>>>();
    scan_batch<<<1, NB>>>();
    fill_csr<<<(NE + 255) / 256, 256>>>();

    dim3 gin((NN + 63) / 64, 2);
    gemm_in<<<gin, 256>>>(x, W_in, b_in);

    int nodes_blocks = (NN * 32 + 255) / 256;
    for (int s = 0; s < MPNN_STEPS; s++)
        mpnn_step<<<nodes_blocks, 256>>>(s & 1);
    // after 4 steps the live buffer is g_h0

    for (int it = 0; it < S2S_STEPS; it++) {
        if (it > 0) {
            dim3 gg(8, 8);
            gemm_gates<<<gg, 256>>>(W_ih, W_hh);
        }
        lstm_pointwise<<<NB, DD>>>(it == 0 ? 1 : 0, b_ih, b_hh);
        e_kernel<<<nodes_blocks, 256>>>();
        graph_reduce<<<NB, DD>>>();
    }
    pred_kernel<<<NB, 32>>>(W_pred, b_pred, out);
    (void)in_sizes; (void)n_in; (void)out_size;
}